// round 4
// baseline (speedup 1.0000x reference)
#include <cuda_runtime.h>
#include <cuda_bf16.h>
#include <math.h>
#include <stdint.h>

// Problem dims (fixed by the dataset)
#define B_ROWS 32768
#define OBS_D  512
#define H1_D   1024
#define H2_D   1024
#define ACT_D  64
#define OUT3_D (2*ACT_D)   // 128

// ---------------- device scratch (no allocs allowed) ----------------
__device__ __nv_bfloat16 g_xb[(size_t)B_ROWS * OBS_D];      // obs in bf16
__device__ __nv_bfloat16 g_h1[(size_t)B_ROWS * H1_D];       // layer1 out
__device__ __nv_bfloat16 g_h2[(size_t)B_ROWS * H2_D];       // layer2 out
__device__ float         g_net[(size_t)B_ROWS * OUT3_D];    // layer3 out (fp32)
__device__ __nv_bfloat16 g_w1[H1_D * OBS_D];                // int-valued quant weights (bf16-exact)
__device__ __nv_bfloat16 g_w2[H2_D * H1_D];
__device__ __nv_bfloat16 g_w3[OUT3_D * H2_D];
__device__ float g_b1q[H1_D], g_b2q[H2_D], g_b3q[OUT3_D];
__device__ float g_absmax[3];
__device__ float g_scales[3];

// ---------------- small prep kernels ----------------
__global__ void zero_absmax_kernel() {
    if (threadIdx.x < 3) g_absmax[threadIdx.x] = 0.0f;
}

__global__ void absmax_kernel(const float* __restrict__ W, int n, int which) {
    float m = 0.0f;
    for (int i = blockIdx.x * blockDim.x + threadIdx.x; i < n; i += gridDim.x * blockDim.x)
        m = fmaxf(m, fabsf(W[i]));
    #pragma unroll
    for (int off = 16; off; off >>= 1)
        m = fmaxf(m, __shfl_xor_sync(0xffffffffu, m, off));
    if ((threadIdx.x & 31) == 0)
        atomicMax(reinterpret_cast<int*>(&g_absmax[which]), __float_as_int(m));
}

// Compute epilogue scales + quantized biases (single block, 1024 threads).
__global__ void prep_kernel(const float* __restrict__ b1,
                            const float* __restrict__ b2,
                            const float* __restrict__ b3) {
    const float s_in = 1.0f / 12000.0f;
    const float ws1 = g_absmax[0] * (1.0f / 127.0f);
    const float ws2 = g_absmax[1] * (1.0f / 127.0f);
    const float ws3 = g_absmax[2] * (1.0f / 127.0f);
    const int t = threadIdx.x;
    if (t == 0) {
        g_scales[0] = s_in * s_in * ws1;   // layer1: x = obs*s_in^2, weight carries ws1
        g_scales[1] = ws2;
        g_scales[2] = ws3;
    }
    const float s1  = s_in * ws1;           // bias scale fc1 = in_scale * w_scale
    const float sb2 = s1 * ws2;
    const float s2  = s1 * ws2;
    const float sb3 = s2 * ws3;
    if (t < H1_D) g_b1q[t] = fminf(fmaxf(rintf(b1[t] / s1), -128.0f), 127.0f) * s1;
    if (t < H2_D) g_b2q[t] = fminf(fmaxf(rintf(b2[t] / sb2), -128.0f), 127.0f) * sb2;
    if (t < OUT3_D) g_b3q[t] = fminf(fmaxf(rintf(b3[t] / sb3), -128.0f), 127.0f) * sb3;
}

// Wq_int = clip(rint(W/s), -127, 127) stored as bf16 (exact small integers).
__global__ void quant_w_kernel(const float* __restrict__ W, __nv_bfloat16* __restrict__ Wq,
                               int n, int which) {
    const float s = g_absmax[which] * (1.0f / 127.0f);
    const float inv = 1.0f / s;
    for (int i = blockIdx.x * blockDim.x + threadIdx.x; i < n; i += gridDim.x * blockDim.x) {
        float v = rintf(W[i] * inv);
        v = fminf(fmaxf(v, -127.0f), 127.0f);
        Wq[i] = __float2bfloat16(v);
    }
}

__global__ void cvt_obs_kernel(const float* __restrict__ src, __nv_bfloat16* __restrict__ dst, int n2) {
    // n2 = n/2, process float2 -> bfloat162
    const float2* s2 = reinterpret_cast<const float2*>(src);
    __nv_bfloat162* d2 = reinterpret_cast<__nv_bfloat162*>(dst);
    for (int i = blockIdx.x * blockDim.x + threadIdx.x; i < n2; i += gridDim.x * blockDim.x) {
        float2 v = s2[i];
        d2[i] = __floats2bfloat162_rn(v.x, v.y);
    }
}

// ---------------- GEMM: C[M,N] = A[M,K] @ Bw[N,K]^T (both bf16, row-major) ----------------
// BM=BN=128, BK=64, 3-stage cp.async pipeline, 256 threads,
// warp layout 4x2 (warp tile 32x64), mma.sync.m16n8k16 bf16, XOR-8 swizzled SMEM.

__device__ __forceinline__ void st2(__nv_bfloat16* C, int r, int c, float v0, float v1, int N) {
    *reinterpret_cast<__nv_bfloat162*>(C + (size_t)r * N + c) = __floats2bfloat162_rn(v0, v1);
}
__device__ __forceinline__ void st2(float* C, int r, int c, float v0, float v1, int N) {
    *reinterpret_cast<float2*>(C + (size_t)r * N + c) = make_float2(v0, v1);
}

template<bool RELU, typename OutT>
__global__ void __launch_bounds__(256, 1)
gemm_tn_kernel(const __nv_bfloat16* __restrict__ A,
               const __nv_bfloat16* __restrict__ Bw,
               OutT* __restrict__ C,
               const float* __restrict__ bias,
               const float* __restrict__ scale_p,
               int M, int N, int K) {
    extern __shared__ char smem[];
    const int tid  = threadIdx.x;
    const int lane = tid & 31;
    const int warp = tid >> 5;
    const int wm = (warp & 3) * 32;   // warp M offset within tile
    const int wn = (warp >> 2) * 64;  // warp N offset within tile
    const int bm = blockIdx.y * 128;
    const int bn = blockIdx.x * 128;
    const unsigned sbase = (unsigned)__cvta_generic_to_shared(smem);
    const unsigned B_OFF = 3u * 16384u;
    const int KT = K >> 6;

    auto load_tile = [&](int kt, int st) {
        const __nv_bfloat16* Ag = A + (size_t)bm * K + kt * 64;
        const __nv_bfloat16* Bg = Bw + (size_t)bn * K + kt * 64;
        unsigned as = sbase + st * 16384u;
        unsigned bs = sbase + B_OFF + st * 16384u;
        #pragma unroll
        for (int i = 0; i < 4; i++) {
            int idx = tid + i * 256;            // 0..1023 (128 rows x 8 chunks of 16B)
            int row = idx >> 3;
            int ch  = idx & 7;
            int sw  = ch ^ (row & 7);
            asm volatile("cp.async.cg.shared.global [%0], [%1], 16;\n" ::
                "r"(as + row * 128 + sw * 16), "l"(Ag + (size_t)row * K + ch * 8));
            asm volatile("cp.async.cg.shared.global [%0], [%1], 16;\n" ::
                "r"(bs + row * 128 + sw * 16), "l"(Bg + (size_t)row * K + ch * 8));
        }
    };

    float acc[2][8][4];
    #pragma unroll
    for (int mi = 0; mi < 2; mi++)
        #pragma unroll
        for (int ni = 0; ni < 8; ni++)
            #pragma unroll
            for (int r = 0; r < 4; r++) acc[mi][ni][r] = 0.0f;

    load_tile(0, 0);
    asm volatile("cp.async.commit_group;\n");
    load_tile(1, 1);
    asm volatile("cp.async.commit_group;\n");

    for (int kt = 0; kt < KT; kt++) {
        asm volatile("cp.async.wait_group 1;\n");
        __syncthreads();
        const int st = kt % 3;
        const unsigned as = sbase + st * 16384u;
        const unsigned bs = sbase + B_OFF + st * 16384u;
        #pragma unroll
        for (int s = 0; s < 4; s++) {           // 4 x k16 per BK=64
            unsigned af[2][4];
            #pragma unroll
            for (int mi = 0; mi < 2; mi++) {
                int row = wm + mi * 16 + (lane & 15);
                int ch  = 2 * s + (lane >> 4);
                unsigned addr = as + row * 128 + ((ch ^ (row & 7)) << 4);
                asm volatile("ldmatrix.sync.aligned.m8n8.x4.shared.b16 {%0,%1,%2,%3}, [%4];\n"
                    : "=r"(af[mi][0]), "=r"(af[mi][1]), "=r"(af[mi][2]), "=r"(af[mi][3])
                    : "r"(addr));
            }
            unsigned bf[8][2];
            #pragma unroll
            for (int nj = 0; nj < 4; nj++) {    // each x4 covers 16 n
                int row = wn + nj * 16 + (lane & 7) + ((lane & 16) >> 1);
                int ch  = 2 * s + ((lane >> 3) & 1);
                unsigned addr = bs + row * 128 + ((ch ^ (row & 7)) << 4);
                asm volatile("ldmatrix.sync.aligned.m8n8.x4.shared.b16 {%0,%1,%2,%3}, [%4];\n"
                    : "=r"(bf[2 * nj][0]), "=r"(bf[2 * nj][1]),
                      "=r"(bf[2 * nj + 1][0]), "=r"(bf[2 * nj + 1][1])
                    : "r"(addr));
            }
            #pragma unroll
            for (int mi = 0; mi < 2; mi++)
                #pragma unroll
                for (int ni = 0; ni < 8; ni++) {
                    asm volatile(
                        "mma.sync.aligned.m16n8k16.row.col.f32.bf16.bf16.f32 "
                        "{%0,%1,%2,%3}, {%4,%5,%6,%7}, {%8,%9}, {%0,%1,%2,%3};\n"
                        : "+f"(acc[mi][ni][0]), "+f"(acc[mi][ni][1]),
                          "+f"(acc[mi][ni][2]), "+f"(acc[mi][ni][3])
                        : "r"(af[mi][0]), "r"(af[mi][1]), "r"(af[mi][2]), "r"(af[mi][3]),
                          "r"(bf[ni][0]), "r"(bf[ni][1]));
                }
        }
        __syncthreads();
        if (kt + 2 < KT) load_tile(kt + 2, (kt + 2) % 3);
        asm volatile("cp.async.commit_group;\n");
    }

    const float scale = *scale_p;
    #pragma unroll
    for (int mi = 0; mi < 2; mi++) {
        #pragma unroll
        for (int ni = 0; ni < 8; ni++) {
            int r0 = bm + wm + mi * 16 + (lane >> 2);
            int c0 = bn + wn + ni * 8 + 2 * (lane & 3);
            float bz0 = bias[c0], bz1 = bias[c0 + 1];
            float v0 = fmaf(acc[mi][ni][0], scale, bz0);
            float v1 = fmaf(acc[mi][ni][1], scale, bz1);
            float v2 = fmaf(acc[mi][ni][2], scale, bz0);
            float v3 = fmaf(acc[mi][ni][3], scale, bz1);
            if (RELU) {
                v0 = fmaxf(v0, 0.0f); v1 = fmaxf(v1, 0.0f);
                v2 = fmaxf(v2, 0.0f); v3 = fmaxf(v3, 0.0f);
            }
            st2(C, r0,     c0, v0, v1, N);
            st2(C, r0 + 8, c0, v2, v3, N);
        }
    }
}

// ---------------- finalize: action + logp ----------------
__global__ void finalize_kernel(const float* __restrict__ eps,
                                float* __restrict__ action,
                                float* __restrict__ logp) {
    const int row = blockIdx.x;
    const int i = threadIdx.x;  // 0..63
    const float* net = g_net + (size_t)row * OUT3_D;
    float mu = net[i];
    float ls = fminf(fmaxf(net[64 + i], -20.0f), 2.0f);
    float sd = expf(ls);
    float e  = eps[(size_t)row * ACT_D + i];
    float pi = fmaf(sd, e, mu);
    action[(size_t)row * ACT_D + i] = 10000.0f * tanhf(pi) / 10000.0f;
    // softplus(-2*pi), numerically stable
    float z  = -2.0f * pi;
    float sp = fmaxf(z, 0.0f) + log1pf(expf(-fabsf(z)));
    float t = -0.5f * e * e - ls - 0.91893853320467274178f
              - 2.0f * (0.69314718055994530942f - pi - sp);
    #pragma unroll
    for (int off = 16; off; off >>= 1) t += __shfl_down_sync(0xffffffffu, t, off);
    __shared__ float ws[2];
    if ((i & 31) == 0) ws[i >> 5] = t;
    __syncthreads();
    if (i == 0) logp[row] = ws[0] + ws[1];
}

// ---------------- launch ----------------
extern "C" void kernel_launch(void* const* d_in, const int* in_sizes, int n_in,
                              void* d_out, int out_size) {
    const float* obs = (const float*)d_in[0];
    const float* eps = (const float*)d_in[1];
    const float* W1  = (const float*)d_in[2];
    const float* b1  = (const float*)d_in[3];
    const float* W2  = (const float*)d_in[4];
    const float* b2  = (const float*)d_in[5];
    const float* W3  = (const float*)d_in[6];
    const float* b3  = (const float*)d_in[7];
    float* out = (float*)d_out;

    void *xb, *h1, *h2, *net, *w1, *w2, *w3, *b1q, *b2q, *b3q, *sc;
    cudaGetSymbolAddress(&xb,  g_xb);
    cudaGetSymbolAddress(&h1,  g_h1);
    cudaGetSymbolAddress(&h2,  g_h2);
    cudaGetSymbolAddress(&net, g_net);
    cudaGetSymbolAddress(&w1,  g_w1);
    cudaGetSymbolAddress(&w2,  g_w2);
    cudaGetSymbolAddress(&w3,  g_w3);
    cudaGetSymbolAddress(&b1q, g_b1q);
    cudaGetSymbolAddress(&b2q, g_b2q);
    cudaGetSymbolAddress(&b3q, g_b3q);
    cudaGetSymbolAddress(&sc,  g_scales);

    const int SMEM = 6 * 16384;  // 96 KB dynamic
    cudaFuncSetAttribute(gemm_tn_kernel<true,  __nv_bfloat16>,
                         cudaFuncAttributeMaxDynamicSharedMemorySize, SMEM);
    cudaFuncSetAttribute(gemm_tn_kernel<false, float>,
                         cudaFuncAttributeMaxDynamicSharedMemorySize, SMEM);

    zero_absmax_kernel<<<1, 32>>>();
    absmax_kernel<<<256, 256>>>(W1, H1_D * OBS_D, 0);
    absmax_kernel<<<256, 256>>>(W2, H2_D * H1_D, 1);
    absmax_kernel<<<64,  256>>>(W3, OUT3_D * H2_D, 2);
    prep_kernel<<<1, 1024>>>(b1, b2, b3);
    quant_w_kernel<<<256, 256>>>(W1, (__nv_bfloat16*)w1, H1_D * OBS_D, 0);
    quant_w_kernel<<<256, 256>>>(W2, (__nv_bfloat16*)w2, H2_D * H1_D, 1);
    quant_w_kernel<<<64,  256>>>(W3, (__nv_bfloat16*)w3, OUT3_D * H2_D, 2);
    cvt_obs_kernel<<<2048, 256>>>(obs, (__nv_bfloat16*)xb, (B_ROWS * OBS_D) / 2);

    gemm_tn_kernel<true, __nv_bfloat16>
        <<<dim3(H1_D / 128, B_ROWS / 128), 256, SMEM>>>(
            (const __nv_bfloat16*)xb, (const __nv_bfloat16*)w1,
            (__nv_bfloat16*)h1, (const float*)b1q, (const float*)sc + 0,
            B_ROWS, H1_D, OBS_D);

    gemm_tn_kernel<true, __nv_bfloat16>
        <<<dim3(H2_D / 128, B_ROWS / 128), 256, SMEM>>>(
            (const __nv_bfloat16*)h1, (const __nv_bfloat16*)w2,
            (__nv_bfloat16*)h2, (const float*)b2q, (const float*)sc + 1,
            B_ROWS, H2_D, H1_D);

    gemm_tn_kernel<false, float>
        <<<dim3(OUT3_D / 128, B_ROWS / 128), 256, SMEM>>>(
            (const __nv_bfloat16*)h2, (const __nv_bfloat16*)w3,
            (float*)net, (const float*)b3q, (const float*)sc + 2,
            B_ROWS, OUT3_D, H2_D);

    finalize_kernel<<<B_ROWS, 64>>>(eps, out, out + (size_t)B_ROWS * ACT_D);
}

// round 7
// speedup vs baseline: 1.2487x; 1.2487x over previous
#include <cuda_runtime.h>
#include <cuda_bf16.h>
#include <math.h>
#include <stdint.h>

// Problem dims (fixed by the dataset)
#define B_ROWS 32768
#define OBS_D  512
#define H1_D   1024
#define H2_D   1024
#define ACT_D  64
#define OUT3_D (2*ACT_D)   // 128

// ---------------- device scratch (no allocs allowed) ----------------
__device__ __align__(256) __nv_bfloat16 g_xb[(size_t)B_ROWS * OBS_D];
__device__ __align__(256) __nv_bfloat16 g_h1[(size_t)B_ROWS * H1_D];
__device__ __align__(256) __nv_bfloat16 g_h2[(size_t)B_ROWS * H2_D];
__device__ __align__(256) __nv_bfloat16 g_w1[H1_D * OBS_D];
__device__ __align__(256) __nv_bfloat16 g_w2[H2_D * H1_D];
__device__ __align__(256) __nv_bfloat16 g_w3[OUT3_D * H2_D];
__device__ float g_b1q[H1_D], g_b2q[H2_D], g_b3q[OUT3_D];
__device__ float g_absmax[3];
__device__ float g_scales[3];

__device__ __forceinline__ uint32_t pack_bf16x2(float lo, float hi) {
    uint32_t r;
    asm("cvt.rn.bf16x2.f32 %0, %1, %2;" : "=r"(r) : "f"(hi), "f"(lo));
    return r;
}

// ---------------- prep kernels (5 launches total before GEMMs) ----------------
__global__ void zero_absmax_kernel() {
    if (threadIdx.x < 3) g_absmax[threadIdx.x] = 0.0f;
}

// blocks [0,64)->W1  [64,192)->W2  [192,208)->W3
__global__ void absmax3_kernel(const float4* __restrict__ W1,
                               const float4* __restrict__ W2,
                               const float4* __restrict__ W3) {
    int b = blockIdx.x;
    const float4* W; int n4, nb, which;
    if (b < 64)       { W = W1; n4 = (H1_D * OBS_D) / 4; nb = 64;  which = 0; }
    else if (b < 192) { W = W2; n4 = (H2_D * H1_D) / 4;  nb = 128; which = 1; b -= 64; }
    else              { W = W3; n4 = (OUT3_D * H2_D) / 4; nb = 16; which = 2; b -= 192; }
    float m = 0.0f;
    for (int i = b * 256 + threadIdx.x; i < n4; i += nb * 256) {
        float4 v = W[i];
        m = fmaxf(m, fmaxf(fmaxf(fabsf(v.x), fabsf(v.y)), fmaxf(fabsf(v.z), fabsf(v.w))));
    }
    #pragma unroll
    for (int off = 16; off; off >>= 1)
        m = fmaxf(m, __shfl_xor_sync(0xffffffffu, m, off));
    if ((threadIdx.x & 31) == 0)
        atomicMax(reinterpret_cast<int*>(&g_absmax[which]), __float_as_int(m));
}

__global__ void prep_kernel(const float* __restrict__ b1,
                            const float* __restrict__ b2,
                            const float* __restrict__ b3) {
    const float s_in = 1.0f / 12000.0f;
    const float ws1 = g_absmax[0] * (1.0f / 127.0f);
    const float ws2 = g_absmax[1] * (1.0f / 127.0f);
    const float ws3 = g_absmax[2] * (1.0f / 127.0f);
    const int t = threadIdx.x;
    if (t == 0) {
        g_scales[0] = s_in * s_in * ws1;
        g_scales[1] = ws2;
        g_scales[2] = ws3;
    }
    const float s1  = s_in * ws1;
    const float sb2 = s1 * ws2;
    const float s2  = s1 * ws2;
    const float sb3 = s2 * ws3;
    if (t < H1_D)   g_b1q[t] = fminf(fmaxf(rintf(b1[t] / s1),  -128.0f), 127.0f) * s1;
    if (t < H2_D)   g_b2q[t] = fminf(fmaxf(rintf(b2[t] / sb2), -128.0f), 127.0f) * sb2;
    if (t < OUT3_D) g_b3q[t] = fminf(fmaxf(rintf(b3[t] / sb3), -128.0f), 127.0f) * sb3;
}

__global__ void quant3_kernel(const float4* __restrict__ W1,
                              const float4* __restrict__ W2,
                              const float4* __restrict__ W3) {
    int b = blockIdx.x;
    const float4* W; uint2* O; int n4, nb, which;
    if (b < 64)       { W = W1; O = (uint2*)g_w1; n4 = (H1_D * OBS_D) / 4; nb = 64;  which = 0; }
    else if (b < 192) { W = W2; O = (uint2*)g_w2; n4 = (H2_D * H1_D) / 4;  nb = 128; which = 1; b -= 64; }
    else              { W = W3; O = (uint2*)g_w3; n4 = (OUT3_D * H2_D) / 4; nb = 16; which = 2; b -= 192; }
    const float inv = 127.0f / g_absmax[which];
    for (int i = b * 256 + threadIdx.x; i < n4; i += nb * 256) {
        float4 v = W[i];
        float q0 = fminf(fmaxf(rintf(v.x * inv), -127.0f), 127.0f);
        float q1 = fminf(fmaxf(rintf(v.y * inv), -127.0f), 127.0f);
        float q2 = fminf(fmaxf(rintf(v.z * inv), -127.0f), 127.0f);
        float q3 = fminf(fmaxf(rintf(v.w * inv), -127.0f), 127.0f);
        uint2 o;
        o.x = pack_bf16x2(q0, q1);
        o.y = pack_bf16x2(q2, q3);
        O[i] = o;
    }
}

__global__ void cvt_obs4_kernel(const float4* __restrict__ src, uint2* __restrict__ dst, int n4) {
    for (int i = blockIdx.x * blockDim.x + threadIdx.x; i < n4; i += gridDim.x * blockDim.x) {
        float4 v = src[i];
        uint2 o;
        o.x = pack_bf16x2(v.x, v.y);
        o.y = pack_bf16x2(v.z, v.w);
        dst[i] = o;
    }
}

// ---------------- GEMM: C[M,N] = A[M,K] @ Bw[N,K]^T (bf16 in, fp32 acc) ----------------
// BM=128, BN/TPB templated, BK=64, 3-stage cp.async pipeline, XOR-8 swizzle,
// warp tile 32x64, mma.sync.m16n8k16.
// MODE 0: epilogue = scale*acc + bias, ReLU, bf16 store to C.
// MODE 1: (BN=128, TPB=256) fused squashed-gaussian actor epilogue -> action/logp.

__device__ __forceinline__ void st2bf(__nv_bfloat16* C, int r, int c, float v0, float v1, int N) {
    *reinterpret_cast<uint32_t*>(C + (size_t)r * N + c) = pack_bf16x2(v0, v1);
}

template<int BN, int TPB, int MODE>
__global__ void __launch_bounds__(TPB, 1)
gemm_tn(const __nv_bfloat16* __restrict__ A,
        const __nv_bfloat16* __restrict__ Bw,
        __nv_bfloat16* __restrict__ C,
        const float* __restrict__ bias,
        const float* __restrict__ scale_p,
        int K, int Nst,
        const float* __restrict__ eps,
        float* __restrict__ action,
        float* __restrict__ logp) {
    extern __shared__ char smem[];
    constexpr unsigned STG = 16384u + BN * 128u;   // A stage 16KB + B stage
    const int tid  = threadIdx.x;
    const int lane = tid & 31;
    const int warp = tid >> 5;
    const int wm = (warp & 3) * 32;
    const int wn = (warp >> 2) * 64;
    const int bm = blockIdx.y * 128;
    const int bn = blockIdx.x * BN;
    const unsigned sbase = (unsigned)__cvta_generic_to_shared(smem);
    const int KT = K >> 6;

    auto load_tile = [&](int c) {
        const int st = c % 3;
        const __nv_bfloat16* Ag = A + (size_t)bm * K + c * 64;
        const __nv_bfloat16* Bg = Bw + (size_t)bn * K + c * 64;
        const unsigned as = sbase + st * STG;
        const unsigned bs = as + 16384u;
        #pragma unroll
        for (int i = 0; i < 1024 / TPB; i++) {          // A: 128 rows x 8 x 16B
            int idx = tid + i * TPB;
            int row = idx >> 3, ch = idx & 7, sw = ch ^ (row & 7);
            asm volatile("cp.async.cg.shared.global [%0], [%1], 16;" ::
                "r"(as + row * 128u + sw * 16u), "l"(Ag + (size_t)row * K + ch * 8));
        }
        #pragma unroll
        for (int i = 0; i < BN * 8 / TPB; i++) {        // B: BN rows x 8 x 16B
            int idx = tid + i * TPB;
            int row = idx >> 3, ch = idx & 7, sw = ch ^ (row & 7);
            asm volatile("cp.async.cg.shared.global [%0], [%1], 16;" ::
                "r"(bs + row * 128u + sw * 16u), "l"(Bg + (size_t)row * K + ch * 8));
        }
    };

    float acc[2][8][4];
    #pragma unroll
    for (int mi = 0; mi < 2; mi++)
        #pragma unroll
        for (int ni = 0; ni < 8; ni++)
            #pragma unroll
            for (int r = 0; r < 4; r++) acc[mi][ni][r] = 0.0f;

    load_tile(0);
    asm volatile("cp.async.commit_group;" ::: "memory");
    load_tile(1);
    asm volatile("cp.async.commit_group;" ::: "memory");

    for (int kt = 0; kt < KT; kt++) {
        asm volatile("cp.async.wait_group 1;" ::: "memory");
        __syncthreads();
        const unsigned as = sbase + (kt % 3) * STG;
        const unsigned bs = as + 16384u;
        #pragma unroll
        for (int s = 0; s < 4; s++) {
            unsigned af[2][4];
            #pragma unroll
            for (int mi = 0; mi < 2; mi++) {
                int row = wm + mi * 16 + (lane & 15);
                int ch  = 2 * s + (lane >> 4);
                unsigned addr = as + row * 128 + ((ch ^ (row & 7)) << 4);
                asm volatile("ldmatrix.sync.aligned.m8n8.x4.shared.b16 {%0,%1,%2,%3}, [%4];"
                    : "=r"(af[mi][0]), "=r"(af[mi][1]), "=r"(af[mi][2]), "=r"(af[mi][3])
                    : "r"(addr));
            }
            unsigned bf[8][2];
            #pragma unroll
            for (int nj = 0; nj < 4; nj++) {
                int row = wn + nj * 16 + (lane & 7) + ((lane & 16) >> 1);
                int ch  = 2 * s + ((lane >> 3) & 1);
                unsigned addr = bs + row * 128 + ((ch ^ (row & 7)) << 4);
                asm volatile("ldmatrix.sync.aligned.m8n8.x4.shared.b16 {%0,%1,%2,%3}, [%4];"
                    : "=r"(bf[2 * nj][0]), "=r"(bf[2 * nj][1]),
                      "=r"(bf[2 * nj + 1][0]), "=r"(bf[2 * nj + 1][1])
                    : "r"(addr));
            }
            #pragma unroll
            for (int mi = 0; mi < 2; mi++)
                #pragma unroll
                for (int ni = 0; ni < 8; ni++) {
                    asm volatile(
                        "mma.sync.aligned.m16n8k16.row.col.f32.bf16.bf16.f32 "
                        "{%0,%1,%2,%3}, {%4,%5,%6,%7}, {%8,%9}, {%0,%1,%2,%3};"
                        : "+f"(acc[mi][ni][0]), "+f"(acc[mi][ni][1]),
                          "+f"(acc[mi][ni][2]), "+f"(acc[mi][ni][3])
                        : "r"(af[mi][0]), "r"(af[mi][1]), "r"(af[mi][2]), "r"(af[mi][3]),
                          "r"(bf[ni][0]), "r"(bf[ni][1]));
                }
        }
        __syncthreads();
        if (kt + 2 < KT) load_tile(kt + 2);
        asm volatile("cp.async.commit_group;" ::: "memory");
    }

    const float scale = *scale_p;

    if constexpr (MODE == 0) {
        #pragma unroll
        for (int mi = 0; mi < 2; mi++) {
            #pragma unroll
            for (int ni = 0; ni < 8; ni++) {
                int r0 = bm + wm + mi * 16 + (lane >> 2);
                int c0 = bn + wn + ni * 8 + 2 * (lane & 3);
                float bz0 = __ldg(&bias[c0]), bz1 = __ldg(&bias[c0 + 1]);
                float v0 = fmaxf(fmaf(acc[mi][ni][0], scale, bz0), 0.0f);
                float v1 = fmaxf(fmaf(acc[mi][ni][1], scale, bz1), 0.0f);
                float v2 = fmaxf(fmaf(acc[mi][ni][2], scale, bz0), 0.0f);
                float v3 = fmaxf(fmaf(acc[mi][ni][3], scale, bz1), 0.0f);
                st2bf(C, r0,     c0, v0, v1, Nst);
                st2bf(C, r0 + 8, c0, v2, v3, Nst);
            }
        }
    } else {
        // Fused actor epilogue. BN=128: wn=0 warps hold mu (net cols 0..63),
        // wn=64 warps hold log_std (net cols 64..127). Exchange ls/std via SMEM.
        asm volatile("cp.async.wait_group 0;" ::: "memory");
        __syncthreads();   // safe to reuse pipeline smem
        constexpr int LSS = 65;  // padded row stride (floats)
        float* ls_s  = (float*)smem;               // [128][65]
        float* std_s = ls_s + 128 * LSS;           // [128][65]
        if (wn == 64) {
            #pragma unroll
            for (int mi = 0; mi < 2; mi++) {
                const int rl = wm + mi * 16 + (lane >> 2);
                #pragma unroll
                for (int ni = 0; ni < 8; ni++) {
                    const int c = ni * 8 + 2 * (lane & 3);
                    float bz0 = __ldg(&bias[64 + c]), bz1 = __ldg(&bias[64 + c + 1]);
                    float l0 = fminf(fmaxf(fmaf(acc[mi][ni][0], scale, bz0), -20.0f), 2.0f);
                    float l1 = fminf(fmaxf(fmaf(acc[mi][ni][1], scale, bz1), -20.0f), 2.0f);
                    float l2 = fminf(fmaxf(fmaf(acc[mi][ni][2], scale, bz0), -20.0f), 2.0f);
                    float l3 = fminf(fmaxf(fmaf(acc[mi][ni][3], scale, bz1), -20.0f), 2.0f);
                    ls_s[rl * LSS + c]           = l0;
                    ls_s[rl * LSS + c + 1]       = l1;
                    ls_s[(rl + 8) * LSS + c]     = l2;
                    ls_s[(rl + 8) * LSS + c + 1] = l3;
                    std_s[rl * LSS + c]           = expf(l0);
                    std_s[rl * LSS + c + 1]       = expf(l1);
                    std_s[(rl + 8) * LSS + c]     = expf(l2);
                    std_s[(rl + 8) * LSS + c + 1] = expf(l3);
                }
            }
        }
        __syncthreads();
        if (wn == 0) {
            float lp[2][2] = {{0.0f, 0.0f}, {0.0f, 0.0f}};
            #pragma unroll
            for (int mi = 0; mi < 2; mi++) {
                const int rl = wm + mi * 16 + (lane >> 2);
                const int m0 = bm + rl, m1 = m0 + 8;
                #pragma unroll
                for (int ni = 0; ni < 8; ni++) {
                    const int c = ni * 8 + 2 * (lane & 3);
                    float bz0 = __ldg(&bias[c]), bz1 = __ldg(&bias[c + 1]);
                    float2 e0 = *reinterpret_cast<const float2*>(eps + (size_t)m0 * ACT_D + c);
                    float2 e1 = *reinterpret_cast<const float2*>(eps + (size_t)m1 * ACT_D + c);
                    float mus[4] = {
                        fmaf(acc[mi][ni][0], scale, bz0), fmaf(acc[mi][ni][1], scale, bz1),
                        fmaf(acc[mi][ni][2], scale, bz0), fmaf(acc[mi][ni][3], scale, bz1)};
                    const int rr[4] = {rl, rl, rl + 8, rl + 8};
                    const int cc[4] = {c, c + 1, c, c + 1};
                    const float ev[4] = {e0.x, e0.y, e1.x, e1.y};
                    float av[4];
                    #pragma unroll
                    for (int e = 0; e < 4; e++) {
                        float sd = std_s[rr[e] * LSS + cc[e]];
                        float ls = ls_s[rr[e] * LSS + cc[e]];
                        float pi = fmaf(sd, ev[e], mus[e]);
                        av[e] = tanhf(pi);
                        float z  = -2.0f * pi;
                        float sp = fmaxf(z, 0.0f) + log1pf(expf(-fabsf(z)));
                        lp[mi][e >> 1] += fmaf(-0.5f * ev[e], ev[e], -ls)
                                        - 0.91893853320467274178f
                                        - 2.0f * (0.69314718055994530942f - pi - sp);
                    }
                    *reinterpret_cast<float2*>(action + (size_t)m0 * ACT_D + c) = make_float2(av[0], av[1]);
                    *reinterpret_cast<float2*>(action + (size_t)m1 * ACT_D + c) = make_float2(av[2], av[3]);
                }
            }
            // reduce each lp over the 4 lanes of the quad (lane&3 varies, row fixed)
            #pragma unroll
            for (int mi = 0; mi < 2; mi++)
                #pragma unroll
                for (int h = 0; h < 2; h++) {
                    lp[mi][h] += __shfl_xor_sync(0xffffffffu, lp[mi][h], 1);
                    lp[mi][h] += __shfl_xor_sync(0xffffffffu, lp[mi][h], 2);
                }
            if ((lane & 3) == 0) {
                #pragma unroll
                for (int mi = 0; mi < 2; mi++) {
                    const int rl = wm + mi * 16 + (lane >> 2);
                    logp[bm + rl]     = lp[mi][0];
                    logp[bm + rl + 8] = lp[mi][1];
                }
            }
        }
    }
}

// ---------------- launch ----------------
extern "C" void kernel_launch(void* const* d_in, const int* in_sizes, int n_in,
                              void* d_out, int out_size) {
    const float* obs = (const float*)d_in[0];
    const float* eps = (const float*)d_in[1];
    const float* W1  = (const float*)d_in[2];
    const float* b1  = (const float*)d_in[3];
    const float* W2  = (const float*)d_in[4];
    const float* b2  = (const float*)d_in[5];
    const float* W3  = (const float*)d_in[6];
    const float* b3  = (const float*)d_in[7];
    float* out = (float*)d_out;

    void *xb, *h1, *h2, *w1, *w2, *w3, *b1q, *b2q, *b3q, *sc;
    cudaGetSymbolAddress(&xb,  g_xb);
    cudaGetSymbolAddress(&h1,  g_h1);
    cudaGetSymbolAddress(&h2,  g_h2);
    cudaGetSymbolAddress(&w1,  g_w1);
    cudaGetSymbolAddress(&w2,  g_w2);
    cudaGetSymbolAddress(&w3,  g_w3);
    cudaGetSymbolAddress(&b1q, g_b1q);
    cudaGetSymbolAddress(&b2q, g_b2q);
    cudaGetSymbolAddress(&b3q, g_b3q);
    cudaGetSymbolAddress(&sc,  g_scales);

    const unsigned SM_BIG = 3u * (16384u + 256u * 128u);   // 147456
    const unsigned SM_FUS = 3u * (16384u + 128u * 128u);   // 98304 (>= 66560 epilogue)
    cudaFuncSetAttribute((const void*)gemm_tn<256, 512, 0>,
                         cudaFuncAttributeMaxDynamicSharedMemorySize, SM_BIG);
    cudaFuncSetAttribute((const void*)gemm_tn<128, 256, 1>,
                         cudaFuncAttributeMaxDynamicSharedMemorySize, SM_FUS);

    zero_absmax_kernel<<<1, 32>>>();
    absmax3_kernel<<<208, 256>>>((const float4*)W1, (const float4*)W2, (const float4*)W3);
    prep_kernel<<<1, 1024>>>(b1, b2, b3);
    quant3_kernel<<<208, 256>>>((const float4*)W1, (const float4*)W2, (const float4*)W3);
    cvt_obs4_kernel<<<4096, 256>>>((const float4*)obs, (uint2*)xb, (B_ROWS * OBS_D) / 4);

    // layer 1: [32768,512] @ [1024,512]^T -> relu bf16
    gemm_tn<256, 512, 0><<<dim3(H1_D / 256, B_ROWS / 128), 512, SM_BIG>>>(
        (const __nv_bfloat16*)xb, (const __nv_bfloat16*)w1, (__nv_bfloat16*)h1,
        (const float*)b1q, (const float*)sc + 0, OBS_D, H1_D, nullptr, nullptr, nullptr);

    // layer 2: [32768,1024] @ [1024,1024]^T -> relu bf16
    gemm_tn<256, 512, 0><<<dim3(H2_D / 256, B_ROWS / 128), 512, SM_BIG>>>(
        (const __nv_bfloat16*)h1, (const __nv_bfloat16*)w2, (__nv_bfloat16*)h2,
        (const float*)b2q, (const float*)sc + 1, H1_D, H2_D, nullptr, nullptr, nullptr);

    // layer 3 fused with actor math: action + logp straight to d_out
    gemm_tn<128, 256, 1><<<dim3(1, B_ROWS / 128), 256, SM_FUS>>>(
        (const __nv_bfloat16*)h2, (const __nv_bfloat16*)w3, nullptr,
        (const float*)b3q, (const float*)sc + 2, H2_D, 0,
        eps, out, out + (size_t)B_ROWS * ACT_D);
}

// round 8
// speedup vs baseline: 1.3321x; 1.0668x over previous
#include <cuda_runtime.h>
#include <cuda_bf16.h>
#include <math.h>
#include <stdint.h>

// Problem dims (fixed by the dataset)
#define B_ROWS 32768
#define OBS_D  512
#define H1_D   1024
#define H2_D   1024
#define ACT_D  64
#define OUT3_D (2*ACT_D)   // 128

// ---------------- device scratch (no allocs allowed) ----------------
__device__ __align__(256) __nv_bfloat16 g_xb[(size_t)B_ROWS * OBS_D];
__device__ __align__(256) __nv_bfloat16 g_h1[(size_t)B_ROWS * H1_D];
__device__ __align__(256) __nv_bfloat16 g_h2[(size_t)B_ROWS * H2_D];
__device__ __align__(256) __nv_bfloat16 g_w1[H1_D * OBS_D];
__device__ __align__(256) __nv_bfloat16 g_w2[H2_D * H1_D];
__device__ __align__(256) __nv_bfloat16 g_w3[OUT3_D * H2_D];
__device__ float g_b1q[H1_D], g_b2q[H2_D], g_b3q[OUT3_D];
__device__ float g_absmax[3];
__device__ float g_scales[3];

__device__ __forceinline__ uint32_t pack_bf16x2(float lo, float hi) {
    uint32_t r;
    asm("cvt.rn.bf16x2.f32 %0, %1, %2;" : "=r"(r) : "f"(hi), "f"(lo));
    return r;
}

// ---------------- prep kernels ----------------
__global__ void zero_absmax_kernel() {
    if (threadIdx.x < 3) g_absmax[threadIdx.x] = 0.0f;
}

// blocks [0,64)->W1  [64,192)->W2  [192,208)->W3
__global__ void absmax3_kernel(const float4* __restrict__ W1,
                               const float4* __restrict__ W2,
                               const float4* __restrict__ W3) {
    int b = blockIdx.x;
    const float4* W; int n4, nb, which;
    if (b < 64)       { W = W1; n4 = (H1_D * OBS_D) / 4; nb = 64;  which = 0; }
    else if (b < 192) { W = W2; n4 = (H2_D * H1_D) / 4;  nb = 128; which = 1; b -= 64; }
    else              { W = W3; n4 = (OUT3_D * H2_D) / 4; nb = 16; which = 2; b -= 192; }
    float m = 0.0f;
    for (int i = b * 256 + threadIdx.x; i < n4; i += nb * 256) {
        float4 v = W[i];
        m = fmaxf(m, fmaxf(fmaxf(fabsf(v.x), fabsf(v.y)), fmaxf(fabsf(v.z), fabsf(v.w))));
    }
    #pragma unroll
    for (int off = 16; off; off >>= 1)
        m = fmaxf(m, __shfl_xor_sync(0xffffffffu, m, off));
    if ((threadIdx.x & 31) == 0)
        atomicMax(reinterpret_cast<int*>(&g_absmax[which]), __float_as_int(m));
}

__global__ void prep_kernel(const float* __restrict__ b1,
                            const float* __restrict__ b2,
                            const float* __restrict__ b3) {
    const float s_in = 1.0f / 12000.0f;
    const float ws1 = g_absmax[0] * (1.0f / 127.0f);
    const float ws2 = g_absmax[1] * (1.0f / 127.0f);
    const float ws3 = g_absmax[2] * (1.0f / 127.0f);
    const int t = threadIdx.x;
    if (t == 0) {
        g_scales[0] = s_in * s_in * ws1;
        g_scales[1] = ws2;
        g_scales[2] = ws3;
    }
    const float s1  = s_in * ws1;
    const float sb2 = s1 * ws2;
    const float s2  = s1 * ws2;
    const float sb3 = s2 * ws3;
    if (t < H1_D)   g_b1q[t] = fminf(fmaxf(rintf(b1[t] / s1),  -128.0f), 127.0f) * s1;
    if (t < H2_D)   g_b2q[t] = fminf(fmaxf(rintf(b2[t] / sb2), -128.0f), 127.0f) * sb2;
    if (t < OUT3_D) g_b3q[t] = fminf(fmaxf(rintf(b3[t] / sb3), -128.0f), 127.0f) * sb3;
}

__global__ void quant3_kernel(const float4* __restrict__ W1,
                              const float4* __restrict__ W2,
                              const float4* __restrict__ W3) {
    int b = blockIdx.x;
    const float4* W; uint2* O; int n4, nb, which;
    if (b < 64)       { W = W1; O = (uint2*)g_w1; n4 = (H1_D * OBS_D) / 4; nb = 64;  which = 0; }
    else if (b < 192) { W = W2; O = (uint2*)g_w2; n4 = (H2_D * H1_D) / 4;  nb = 128; which = 1; b -= 64; }
    else              { W = W3; O = (uint2*)g_w3; n4 = (OUT3_D * H2_D) / 4; nb = 16; which = 2; b -= 192; }
    const float inv = 127.0f / g_absmax[which];
    for (int i = b * 256 + threadIdx.x; i < n4; i += nb * 256) {
        float4 v = W[i];
        float q0 = fminf(fmaxf(rintf(v.x * inv), -127.0f), 127.0f);
        float q1 = fminf(fmaxf(rintf(v.y * inv), -127.0f), 127.0f);
        float q2 = fminf(fmaxf(rintf(v.z * inv), -127.0f), 127.0f);
        float q3 = fminf(fmaxf(rintf(v.w * inv), -127.0f), 127.0f);
        uint2 o;
        o.x = pack_bf16x2(q0, q1);
        o.y = pack_bf16x2(q2, q3);
        O[i] = o;
    }
}

__global__ void cvt_obs4_kernel(const float4* __restrict__ src, uint2* __restrict__ dst, int n4) {
    for (int i = blockIdx.x * blockDim.x + threadIdx.x; i < n4; i += gridDim.x * blockDim.x) {
        float4 v = src[i];
        uint2 o;
        o.x = pack_bf16x2(v.x, v.y);
        o.y = pack_bf16x2(v.z, v.w);
        dst[i] = o;
    }
}

// ---------------- GEMM: C[M,N] = A[M,K] @ Bw[N,K]^T (bf16 in, fp32 acc) ----------------
// BM=BN=128, TPB=256, BK=64, 3-stage cp.async, XOR-8 swizzle, warp tile 32x64,
// mma.sync.m16n8k16, __launch_bounds__(256,2) -> 2 CTAs/SM (96KB smem each).
// Single __syncthreads per K-chunk; next tile's cp.async issued before MMA.
// MODE 0: epilogue = scale*acc + bias, ReLU, bf16 store to C.
// MODE 1: fused squashed-gaussian actor epilogue -> action/logp.

__device__ __forceinline__ void st2bf(__nv_bfloat16* C, int r, int c, float v0, float v1, int N) {
    *reinterpret_cast<uint32_t*>(C + (size_t)r * N + c) = pack_bf16x2(v0, v1);
}

template<int MODE>
__global__ void __launch_bounds__(256, 2)
gemm_tn(const __nv_bfloat16* __restrict__ A,
        const __nv_bfloat16* __restrict__ Bw,
        __nv_bfloat16* __restrict__ C,
        const float* __restrict__ bias,
        const float* __restrict__ scale_p,
        int K, int Nst,
        const float* __restrict__ eps,
        float* __restrict__ action,
        float* __restrict__ logp) {
    extern __shared__ char smem[];
    constexpr unsigned STG = 32768u;                 // 16KB A + 16KB B per stage
    const int tid  = threadIdx.x;
    const int lane = tid & 31;
    const int warp = tid >> 5;
    const int wm = (warp & 3) * 32;                  // 4 warps in M
    const int wn = (warp >> 2) * 64;                 // 2 warps in N
    const int bm = blockIdx.y * 128;
    const int bn = blockIdx.x * 128;
    const unsigned sbase = (unsigned)__cvta_generic_to_shared(smem);
    const int KT = K >> 6;

    auto load_tile = [&](int c) {
        const int st = c % 3;
        const __nv_bfloat16* Ag = A + (size_t)bm * K + c * 64;
        const __nv_bfloat16* Bg = Bw + (size_t)bn * K + c * 64;
        const unsigned as = sbase + st * STG;
        const unsigned bs = as + 16384u;
        #pragma unroll
        for (int i = 0; i < 4; i++) {                // A: 128 rows x 8 x 16B
            int idx = tid + i * 256;
            int row = idx >> 3, ch = idx & 7, sw = ch ^ (row & 7);
            asm volatile("cp.async.cg.shared.global [%0], [%1], 16;" ::
                "r"(as + row * 128u + sw * 16u), "l"(Ag + (size_t)row * K + ch * 8));
        }
        #pragma unroll
        for (int i = 0; i < 4; i++) {                // B: 128 rows x 8 x 16B
            int idx = tid + i * 256;
            int row = idx >> 3, ch = idx & 7, sw = ch ^ (row & 7);
            asm volatile("cp.async.cg.shared.global [%0], [%1], 16;" ::
                "r"(bs + row * 128u + sw * 16u), "l"(Bg + (size_t)row * K + ch * 8));
        }
    };

    float acc[2][8][4];
    #pragma unroll
    for (int mi = 0; mi < 2; mi++)
        #pragma unroll
        for (int ni = 0; ni < 8; ni++)
            #pragma unroll
            for (int r = 0; r < 4; r++) acc[mi][ni][r] = 0.0f;

    load_tile(0);
    asm volatile("cp.async.commit_group;" ::: "memory");
    load_tile(1);
    asm volatile("cp.async.commit_group;" ::: "memory");

    for (int kt = 0; kt < KT; kt++) {
        // chunk kt is complete once at most 1 newer group is pending
        asm volatile("cp.async.wait_group 1;" ::: "memory");
        // all warps have finished MMA(kt-1) on reaching here -> stage (kt+2)%3
        // (== (kt-1)%3) is free for the prefetch below; data of chunk kt visible.
        __syncthreads();
        if (kt + 2 < KT) load_tile(kt + 2);
        asm volatile("cp.async.commit_group;" ::: "memory");

        const unsigned as = sbase + (kt % 3) * STG;
        const unsigned bs = as + 16384u;
        #pragma unroll
        for (int s = 0; s < 4; s++) {
            unsigned af[2][4];
            #pragma unroll
            for (int mi = 0; mi < 2; mi++) {
                int row = wm + mi * 16 + (lane & 15);
                int ch  = 2 * s + (lane >> 4);
                unsigned addr = as + row * 128 + ((ch ^ (row & 7)) << 4);
                asm volatile("ldmatrix.sync.aligned.m8n8.x4.shared.b16 {%0,%1,%2,%3}, [%4];"
                    : "=r"(af[mi][0]), "=r"(af[mi][1]), "=r"(af[mi][2]), "=r"(af[mi][3])
                    : "r"(addr));
            }
            unsigned bf[8][2];
            #pragma unroll
            for (int nj = 0; nj < 4; nj++) {
                int row = wn + nj * 16 + (lane & 7) + ((lane & 16) >> 1);
                int ch  = 2 * s + ((lane >> 3) & 1);
                unsigned addr = bs + row * 128 + ((ch ^ (row & 7)) << 4);
                asm volatile("ldmatrix.sync.aligned.m8n8.x4.shared.b16 {%0,%1,%2,%3}, [%4];"
                    : "=r"(bf[2 * nj][0]), "=r"(bf[2 * nj][1]),
                      "=r"(bf[2 * nj + 1][0]), "=r"(bf[2 * nj + 1][1])
                    : "r"(addr));
            }
            #pragma unroll
            for (int mi = 0; mi < 2; mi++)
                #pragma unroll
                for (int ni = 0; ni < 8; ni++) {
                    asm volatile(
                        "mma.sync.aligned.m16n8k16.row.col.f32.bf16.bf16.f32 "
                        "{%0,%1,%2,%3}, {%4,%5,%6,%7}, {%8,%9}, {%0,%1,%2,%3};"
                        : "+f"(acc[mi][ni][0]), "+f"(acc[mi][ni][1]),
                          "+f"(acc[mi][ni][2]), "+f"(acc[mi][ni][3])
                        : "r"(af[mi][0]), "r"(af[mi][1]), "r"(af[mi][2]), "r"(af[mi][3]),
                          "r"(bf[ni][0]), "r"(bf[ni][1]));
                }
        }
    }

    const float scale = *scale_p;

    if constexpr (MODE == 0) {
        #pragma unroll
        for (int mi = 0; mi < 2; mi++) {
            #pragma unroll
            for (int ni = 0; ni < 8; ni++) {
                int r0 = bm + wm + mi * 16 + (lane >> 2);
                int c0 = bn + wn + ni * 8 + 2 * (lane & 3);
                float bz0 = __ldg(&bias[c0]), bz1 = __ldg(&bias[c0 + 1]);
                float v0 = fmaxf(fmaf(acc[mi][ni][0], scale, bz0), 0.0f);
                float v1 = fmaxf(fmaf(acc[mi][ni][1], scale, bz1), 0.0f);
                float v2 = fmaxf(fmaf(acc[mi][ni][2], scale, bz0), 0.0f);
                float v3 = fmaxf(fmaf(acc[mi][ni][3], scale, bz1), 0.0f);
                st2bf(C, r0,     c0, v0, v1, Nst);
                st2bf(C, r0 + 8, c0, v2, v3, Nst);
            }
        }
    } else {
        // Fused actor epilogue. wn=0 warps hold mu (cols 0..63),
        // wn=64 warps hold log_std (cols 64..127). Exchange ls/std via SMEM.
        asm volatile("cp.async.wait_group 0;" ::: "memory");
        __syncthreads();   // pipeline smem now reusable
        constexpr int LSS = 65;  // padded row stride (floats)
        float* ls_s  = (float*)smem;               // [128][65]
        float* std_s = ls_s + 128 * LSS;           // [128][65]
        if (wn == 64) {
            #pragma unroll
            for (int mi = 0; mi < 2; mi++) {
                const int rl = wm + mi * 16 + (lane >> 2);
                #pragma unroll
                for (int ni = 0; ni < 8; ni++) {
                    const int c = ni * 8 + 2 * (lane & 3);
                    float bz0 = __ldg(&bias[64 + c]), bz1 = __ldg(&bias[64 + c + 1]);
                    float l0 = fminf(fmaxf(fmaf(acc[mi][ni][0], scale, bz0), -20.0f), 2.0f);
                    float l1 = fminf(fmaxf(fmaf(acc[mi][ni][1], scale, bz1), -20.0f), 2.0f);
                    float l2 = fminf(fmaxf(fmaf(acc[mi][ni][2], scale, bz0), -20.0f), 2.0f);
                    float l3 = fminf(fmaxf(fmaf(acc[mi][ni][3], scale, bz1), -20.0f), 2.0f);
                    ls_s[rl * LSS + c]           = l0;
                    ls_s[rl * LSS + c + 1]       = l1;
                    ls_s[(rl + 8) * LSS + c]     = l2;
                    ls_s[(rl + 8) * LSS + c + 1] = l3;
                    std_s[rl * LSS + c]           = expf(l0);
                    std_s[rl * LSS + c + 1]       = expf(l1);
                    std_s[(rl + 8) * LSS + c]     = expf(l2);
                    std_s[(rl + 8) * LSS + c + 1] = expf(l3);
                }
            }
        }
        __syncthreads();
        if (wn == 0) {
            float lp[2][2] = {{0.0f, 0.0f}, {0.0f, 0.0f}};
            #pragma unroll
            for (int mi = 0; mi < 2; mi++) {
                const int rl = wm + mi * 16 + (lane >> 2);
                const int m0 = bm + rl, m1 = m0 + 8;
                #pragma unroll
                for (int ni = 0; ni < 8; ni++) {
                    const int c = ni * 8 + 2 * (lane & 3);
                    float bz0 = __ldg(&bias[c]), bz1 = __ldg(&bias[c + 1]);
                    float2 e0 = *reinterpret_cast<const float2*>(eps + (size_t)m0 * ACT_D + c);
                    float2 e1 = *reinterpret_cast<const float2*>(eps + (size_t)m1 * ACT_D + c);
                    float mus[4] = {
                        fmaf(acc[mi][ni][0], scale, bz0), fmaf(acc[mi][ni][1], scale, bz1),
                        fmaf(acc[mi][ni][2], scale, bz0), fmaf(acc[mi][ni][3], scale, bz1)};
                    const int rr[4] = {rl, rl, rl + 8, rl + 8};
                    const int cc[4] = {c, c + 1, c, c + 1};
                    const float ev[4] = {e0.x, e0.y, e1.x, e1.y};
                    float av[4];
                    #pragma unroll
                    for (int e = 0; e < 4; e++) {
                        float sd = std_s[rr[e] * LSS + cc[e]];
                        float ls = ls_s[rr[e] * LSS + cc[e]];
                        float pi = fmaf(sd, ev[e], mus[e]);
                        av[e] = tanhf(pi);
                        float z  = -2.0f * pi;
                        float sp = fmaxf(z, 0.0f) + log1pf(expf(-fabsf(z)));
                        lp[mi][e >> 1] += fmaf(-0.5f * ev[e], ev[e], -ls)
                                        - 0.91893853320467274178f
                                        - 2.0f * (0.69314718055994530942f - pi - sp);
                    }
                    *reinterpret_cast<float2*>(action + (size_t)m0 * ACT_D + c) = make_float2(av[0], av[1]);
                    *reinterpret_cast<float2*>(action + (size_t)m1 * ACT_D + c) = make_float2(av[2], av[3]);
                }
            }
            #pragma unroll
            for (int mi = 0; mi < 2; mi++)
                #pragma unroll
                for (int h = 0; h < 2; h++) {
                    lp[mi][h] += __shfl_xor_sync(0xffffffffu, lp[mi][h], 1);
                    lp[mi][h] += __shfl_xor_sync(0xffffffffu, lp[mi][h], 2);
                }
            if ((lane & 3) == 0) {
                #pragma unroll
                for (int mi = 0; mi < 2; mi++) {
                    const int rl = wm + mi * 16 + (lane >> 2);
                    logp[bm + rl]     = lp[mi][0];
                    logp[bm + rl + 8] = lp[mi][1];
                }
            }
        }
    }
}

// ---------------- launch ----------------
extern "C" void kernel_launch(void* const* d_in, const int* in_sizes, int n_in,
                              void* d_out, int out_size) {
    const float* obs = (const float*)d_in[0];
    const float* eps = (const float*)d_in[1];
    const float* W1  = (const float*)d_in[2];
    const float* b1  = (const float*)d_in[3];
    const float* W2  = (const float*)d_in[4];
    const float* b2  = (const float*)d_in[5];
    const float* W3  = (const float*)d_in[6];
    const float* b3  = (const float*)d_in[7];
    float* out = (float*)d_out;

    void *xb, *h1, *h2, *w1, *w2, *w3, *b1q, *b2q, *b3q, *sc;
    cudaGetSymbolAddress(&xb,  g_xb);
    cudaGetSymbolAddress(&h1,  g_h1);
    cudaGetSymbolAddress(&h2,  g_h2);
    cudaGetSymbolAddress(&w1,  g_w1);
    cudaGetSymbolAddress(&w2,  g_w2);
    cudaGetSymbolAddress(&w3,  g_w3);
    cudaGetSymbolAddress(&b1q, g_b1q);
    cudaGetSymbolAddress(&b2q, g_b2q);
    cudaGetSymbolAddress(&b3q, g_b3q);
    cudaGetSymbolAddress(&sc,  g_scales);

    const unsigned SMEM = 3u * 32768u;   // 96 KB -> 2 CTAs/SM
    cudaFuncSetAttribute((const void*)gemm_tn<0>,
                         cudaFuncAttributeMaxDynamicSharedMemorySize, SMEM);
    cudaFuncSetAttribute((const void*)gemm_tn<1>,
                         cudaFuncAttributeMaxDynamicSharedMemorySize, SMEM);

    zero_absmax_kernel<<<1, 32>>>();
    absmax3_kernel<<<208, 256>>>((const float4*)W1, (const float4*)W2, (const float4*)W3);
    prep_kernel<<<1, 1024>>>(b1, b2, b3);
    quant3_kernel<<<208, 256>>>((const float4*)W1, (const float4*)W2, (const float4*)W3);
    cvt_obs4_kernel<<<4096, 256>>>((const float4*)obs, (uint2*)xb, (B_ROWS * OBS_D) / 4);

    // layer 1: [32768,512] @ [1024,512]^T -> relu bf16
    gemm_tn<0><<<dim3(H1_D / 128, B_ROWS / 128), 256, SMEM>>>(
        (const __nv_bfloat16*)xb, (const __nv_bfloat16*)w1, (__nv_bfloat16*)h1,
        (const float*)b1q, (const float*)sc + 0, OBS_D, H1_D, nullptr, nullptr, nullptr);

    // layer 2: [32768,1024] @ [1024,1024]^T -> relu bf16
    gemm_tn<0><<<dim3(H2_D / 128, B_ROWS / 128), 256, SMEM>>>(
        (const __nv_bfloat16*)h1, (const __nv_bfloat16*)w2, (__nv_bfloat16*)h2,
        (const float*)b2q, (const float*)sc + 1, H1_D, H2_D, nullptr, nullptr, nullptr);

    // layer 3 fused with actor math: action + logp straight to d_out
    gemm_tn<1><<<dim3(1, B_ROWS / 128), 256, SMEM>>>(
        (const __nv_bfloat16*)h2, (const __nv_bfloat16*)w3, nullptr,
        (const float*)b3q, (const float*)sc + 2, H2_D, 0,
        eps, out, out + (size_t)B_ROWS * ACT_D);
}

// round 10
// speedup vs baseline: 1.3899x; 1.0434x over previous
#include <cuda_runtime.h>
#include <cuda_fp16.h>
#include <math.h>
#include <stdint.h>

// Problem dims (fixed by the dataset)
#define B_ROWS 32768
#define OBS_D  512
#define H1_D   1024
#define H2_D   1024
#define ACT_D  64
#define OUT3_D (2*ACT_D)   // 128

// Activation rescale: hidden activations (~2e-5) are fp16-subnormal, so store
// h*4096 (exact power of two) and fold 1/4096 into the next layer's scale.
#define HSCALE 4096.0f

// ---------------- device scratch (no allocs allowed) ----------------
__device__ __align__(256) __half g_xb[(size_t)B_ROWS * OBS_D];
__device__ __align__(256) __half g_h1[(size_t)B_ROWS * H1_D];
__device__ __align__(256) __half g_h2[(size_t)B_ROWS * H2_D];
__device__ __align__(256) __half g_w1[H1_D * OBS_D];     // int-valued quant weights (fp16-exact)
__device__ __align__(256) __half g_w2[H2_D * H1_D];
__device__ __align__(256) __half g_w3[OUT3_D * H2_D];
__device__ float g_b1q[H1_D], g_b2q[H2_D], g_b3q[OUT3_D];
__device__ float g_absmax[3];
__device__ float g_scales[3];

__device__ __forceinline__ uint32_t pack_h2(float lo, float hi) {
    uint32_t r;
    asm("cvt.rn.f16x2.f32 %0, %1, %2;" : "=r"(r) : "f"(hi), "f"(lo));
    return r;
}

// ---------------- prep kernels ----------------
__global__ void zero_absmax_kernel() {
    if (threadIdx.x < 3) g_absmax[threadIdx.x] = 0.0f;
}

// blocks [0,64)->W1  [64,192)->W2  [192,208)->W3
__global__ void absmax3_kernel(const float4* __restrict__ W1,
                               const float4* __restrict__ W2,
                               const float4* __restrict__ W3) {
    int b = blockIdx.x;
    const float4* W; int n4, nb, which;
    if (b < 64)       { W = W1; n4 = (H1_D * OBS_D) / 4; nb = 64;  which = 0; }
    else if (b < 192) { W = W2; n4 = (H2_D * H1_D) / 4;  nb = 128; which = 1; b -= 64; }
    else              { W = W3; n4 = (OUT3_D * H2_D) / 4; nb = 16; which = 2; b -= 192; }
    float m = 0.0f;
    for (int i = b * 256 + threadIdx.x; i < n4; i += nb * 256) {
        float4 v = W[i];
        m = fmaxf(m, fmaxf(fmaxf(fabsf(v.x), fabsf(v.y)), fmaxf(fabsf(v.z), fabsf(v.w))));
    }
    #pragma unroll
    for (int off = 16; off; off >>= 1)
        m = fmaxf(m, __shfl_xor_sync(0xffffffffu, m, off));
    if ((threadIdx.x & 31) == 0)
        atomicMax(reinterpret_cast<int*>(&g_absmax[which]), __float_as_int(m));
}

__global__ void prep_kernel(const float* __restrict__ b1,
                            const float* __restrict__ b2,
                            const float* __restrict__ b3) {
    const float s_in = 1.0f / 12000.0f;
    const float ws1 = g_absmax[0] * (1.0f / 127.0f);
    const float ws2 = g_absmax[1] * (1.0f / 127.0f);
    const float ws3 = g_absmax[2] * (1.0f / 127.0f);
    const int t = threadIdx.x;
    if (t == 0) {
        g_scales[0] = s_in * s_in * ws1 * HSCALE;  // layer1 out pre-scaled by 4096
        g_scales[1] = ws2;                          // 4096 in / 4096 out cancel
        g_scales[2] = ws3 / HSCALE;                 // undo input prescale
    }
    const float s1  = s_in * ws1;
    const float sb2 = s1 * ws2;
    const float s2  = s1 * ws2;
    const float sb3 = s2 * ws3;
    // biases for layers 1,2 folded with the 4096 output prescale (ReLU commutes)
    if (t < H1_D)   g_b1q[t] = fminf(fmaxf(rintf(b1[t] / s1),  -128.0f), 127.0f) * s1  * HSCALE;
    if (t < H2_D)   g_b2q[t] = fminf(fmaxf(rintf(b2[t] / sb2), -128.0f), 127.0f) * sb2 * HSCALE;
    if (t < OUT3_D) g_b3q[t] = fminf(fmaxf(rintf(b3[t] / sb3), -128.0f), 127.0f) * sb3;
}

__global__ void quant3_kernel(const float4* __restrict__ W1,
                              const float4* __restrict__ W2,
                              const float4* __restrict__ W3) {
    int b = blockIdx.x;
    const float4* W; uint2* O; int n4, nb, which;
    if (b < 64)       { W = W1; O = (uint2*)g_w1; n4 = (H1_D * OBS_D) / 4; nb = 64;  which = 0; }
    else if (b < 192) { W = W2; O = (uint2*)g_w2; n4 = (H2_D * H1_D) / 4;  nb = 128; which = 1; b -= 64; }
    else              { W = W3; O = (uint2*)g_w3; n4 = (OUT3_D * H2_D) / 4; nb = 16; which = 2; b -= 192; }
    const float inv = 127.0f / g_absmax[which];
    for (int i = b * 256 + threadIdx.x; i < n4; i += nb * 256) {
        float4 v = W[i];
        float q0 = fminf(fmaxf(rintf(v.x * inv), -127.0f), 127.0f);
        float q1 = fminf(fmaxf(rintf(v.y * inv), -127.0f), 127.0f);
        float q2 = fminf(fmaxf(rintf(v.z * inv), -127.0f), 127.0f);
        float q3 = fminf(fmaxf(rintf(v.w * inv), -127.0f), 127.0f);
        uint2 o;
        o.x = pack_h2(q0, q1);
        o.y = pack_h2(q2, q3);
        O[i] = o;
    }
}

__global__ void cvt_obs4_kernel(const float4* __restrict__ src, uint2* __restrict__ dst, int n4) {
    for (int i = blockIdx.x * blockDim.x + threadIdx.x; i < n4; i += gridDim.x * blockDim.x) {
        float4 v = src[i];
        uint2 o;
        o.x = pack_h2(v.x, v.y);
        o.y = pack_h2(v.z, v.w);
        dst[i] = o;
    }
}

// ---------------- GEMM: C[M,N] = A[M,K] @ Bw[N,K]^T (fp16 in, FP16 ACC) ----------------
// BM=BN=128, TPB=256, BK=64, 3-stage cp.async, XOR-8 swizzle, warp tile 32x64,
// mma.sync.m16n8k16.f16 (2x rate vs f32-acc), __launch_bounds__(256,2) -> 2 CTAs/SM.
// MODE 0: epilogue = scale*acc + bias, ReLU, fp16 store to C.
// MODE 1: fused squashed-gaussian actor epilogue -> action/logp.

template<int MODE>
__global__ void __launch_bounds__(256, 2)
gemm_tn(const __half* __restrict__ A,
        const __half* __restrict__ Bw,
        __half* __restrict__ C,
        const float* __restrict__ bias,
        const float* __restrict__ scale_p,
        int K, int Nst,
        const float* __restrict__ eps,
        float* __restrict__ action,
        float* __restrict__ logp) {
    extern __shared__ char smem[];
    constexpr unsigned STG = 32768u;                 // 16KB A + 16KB B per stage
    const int tid  = threadIdx.x;
    const int lane = tid & 31;
    const int warp = tid >> 5;
    const int wm = (warp & 3) * 32;                  // 4 warps in M
    const int wn = (warp >> 2) * 64;                 // 2 warps in N
    const int bm = blockIdx.y * 128;
    const int bn = blockIdx.x * 128;
    const unsigned sbase = (unsigned)__cvta_generic_to_shared(smem);
    const int KT = K >> 6;

    auto load_tile = [&](int c) {
        const int st = c % 3;
        const __half* Ag = A + (size_t)bm * K + c * 64;
        const __half* Bg = Bw + (size_t)bn * K + c * 64;
        const unsigned as = sbase + st * STG;
        const unsigned bs = as + 16384u;
        #pragma unroll
        for (int i = 0; i < 4; i++) {                // A: 128 rows x 8 x 16B
            int idx = tid + i * 256;
            int row = idx >> 3, ch = idx & 7, sw = ch ^ (row & 7);
            asm volatile("cp.async.cg.shared.global [%0], [%1], 16;" ::
                "r"(as + row * 128u + sw * 16u), "l"(Ag + (size_t)row * K + ch * 8));
        }
        #pragma unroll
        for (int i = 0; i < 4; i++) {                // B: 128 rows x 8 x 16B
            int idx = tid + i * 256;
            int row = idx >> 3, ch = idx & 7, sw = ch ^ (row & 7);
            asm volatile("cp.async.cg.shared.global [%0], [%1], 16;" ::
                "r"(bs + row * 128u + sw * 16u), "l"(Bg + (size_t)row * K + ch * 8));
        }
    };

    // fp16 accumulators: 2 b32 regs (4 halves) per 16x8 mma
    uint32_t acc[2][8][2];
    #pragma unroll
    for (int mi = 0; mi < 2; mi++)
        #pragma unroll
        for (int ni = 0; ni < 8; ni++) { acc[mi][ni][0] = 0u; acc[mi][ni][1] = 0u; }

    load_tile(0);
    asm volatile("cp.async.commit_group;" ::: "memory");
    load_tile(1);
    asm volatile("cp.async.commit_group;" ::: "memory");

    for (int kt = 0; kt < KT; kt++) {
        asm volatile("cp.async.wait_group 1;" ::: "memory");
        __syncthreads();
        if (kt + 2 < KT) load_tile(kt + 2);
        asm volatile("cp.async.commit_group;" ::: "memory");

        const unsigned as = sbase + (kt % 3) * STG;
        const unsigned bs = as + 16384u;
        #pragma unroll
        for (int s = 0; s < 4; s++) {
            unsigned af[2][4];
            #pragma unroll
            for (int mi = 0; mi < 2; mi++) {
                int row = wm + mi * 16 + (lane & 15);
                int ch  = 2 * s + (lane >> 4);
                unsigned addr = as + row * 128 + ((ch ^ (row & 7)) << 4);
                asm volatile("ldmatrix.sync.aligned.m8n8.x4.shared.b16 {%0,%1,%2,%3}, [%4];"
                    : "=r"(af[mi][0]), "=r"(af[mi][1]), "=r"(af[mi][2]), "=r"(af[mi][3])
                    : "r"(addr));
            }
            unsigned bf[8][2];
            #pragma unroll
            for (int nj = 0; nj < 4; nj++) {
                int row = wn + nj * 16 + (lane & 7) + ((lane & 16) >> 1);
                int ch  = 2 * s + ((lane >> 3) & 1);
                unsigned addr = bs + row * 128 + ((ch ^ (row & 7)) << 4);
                asm volatile("ldmatrix.sync.aligned.m8n8.x4.shared.b16 {%0,%1,%2,%3}, [%4];"
                    : "=r"(bf[2 * nj][0]), "=r"(bf[2 * nj][1]),
                      "=r"(bf[2 * nj + 1][0]), "=r"(bf[2 * nj + 1][1])
                    : "r"(addr));
            }
            #pragma unroll
            for (int mi = 0; mi < 2; mi++)
                #pragma unroll
                for (int ni = 0; ni < 8; ni++) {
                    asm volatile(
                        "mma.sync.aligned.m16n8k16.row.col.f16.f16.f16.f16 "
                        "{%0,%1}, {%2,%3,%4,%5}, {%6,%7}, {%0,%1};"
                        : "+r"(acc[mi][ni][0]), "+r"(acc[mi][ni][1])
                        : "r"(af[mi][0]), "r"(af[mi][1]), "r"(af[mi][2]), "r"(af[mi][3]),
                          "r"(bf[ni][0]), "r"(bf[ni][1]));
                }
        }
    }

    const float scale = *scale_p;

    if constexpr (MODE == 0) {
        #pragma unroll
        for (int mi = 0; mi < 2; mi++) {
            #pragma unroll
            for (int ni = 0; ni < 8; ni++) {
                int r0 = bm + wm + mi * 16 + (lane >> 2);
                int c0 = bn + wn + ni * 8 + 2 * (lane & 3);
                float bz0 = __ldg(&bias[c0]), bz1 = __ldg(&bias[c0 + 1]);
                float2 a01 = __half22float2(*reinterpret_cast<__half2*>(&acc[mi][ni][0]));
                float2 a23 = __half22float2(*reinterpret_cast<__half2*>(&acc[mi][ni][1]));
                float v0 = fmaxf(fmaf(a01.x, scale, bz0), 0.0f);
                float v1 = fmaxf(fmaf(a01.y, scale, bz1), 0.0f);
                float v2 = fmaxf(fmaf(a23.x, scale, bz0), 0.0f);
                float v3 = fmaxf(fmaf(a23.y, scale, bz1), 0.0f);
                *reinterpret_cast<uint32_t*>(C + (size_t)r0 * Nst + c0)       = pack_h2(v0, v1);
                *reinterpret_cast<uint32_t*>(C + (size_t)(r0 + 8) * Nst + c0) = pack_h2(v2, v3);
            }
        }
    } else {
        // Fused actor epilogue. wn=0 warps hold mu (cols 0..63),
        // wn=64 warps hold log_std (cols 64..127). Exchange ls/std via SMEM.
        asm volatile("cp.async.wait_group 0;" ::: "memory");
        __syncthreads();   // pipeline smem now reusable
        constexpr int LSS = 65;  // padded row stride (floats)
        float* ls_s  = (float*)smem;               // [128][65]
        float* std_s = ls_s + 128 * LSS;           // [128][65]
        if (wn == 64) {
            #pragma unroll
            for (int mi = 0; mi < 2; mi++) {
                const int rl = wm + mi * 16 + (lane >> 2);
                #pragma unroll
                for (int ni = 0; ni < 8; ni++) {
                    const int c = ni * 8 + 2 * (lane & 3);
                    float bz0 = __ldg(&bias[64 + c]), bz1 = __ldg(&bias[64 + c + 1]);
                    float2 a01 = __half22float2(*reinterpret_cast<__half2*>(&acc[mi][ni][0]));
                    float2 a23 = __half22float2(*reinterpret_cast<__half2*>(&acc[mi][ni][1]));
                    float l0 = fminf(fmaxf(fmaf(a01.x, scale, bz0), -20.0f), 2.0f);
                    float l1 = fminf(fmaxf(fmaf(a01.y, scale, bz1), -20.0f), 2.0f);
                    float l2 = fminf(fmaxf(fmaf(a23.x, scale, bz0), -20.0f), 2.0f);
                    float l3 = fminf(fmaxf(fmaf(a23.y, scale, bz1), -20.0f), 2.0f);
                    ls_s[rl * LSS + c]           = l0;
                    ls_s[rl * LSS + c + 1]       = l1;
                    ls_s[(rl + 8) * LSS + c]     = l2;
                    ls_s[(rl + 8) * LSS + c + 1] = l3;
                    std_s[rl * LSS + c]           = expf(l0);
                    std_s[rl * LSS + c + 1]       = expf(l1);
                    std_s[(rl + 8) * LSS + c]     = expf(l2);
                    std_s[(rl + 8) * LSS + c + 1] = expf(l3);
                }
            }
        }
        __syncthreads();
        if (wn == 0) {
            float lp[2][2] = {{0.0f, 0.0f}, {0.0f, 0.0f}};
            #pragma unroll
            for (int mi = 0; mi < 2; mi++) {
                const int rl = wm + mi * 16 + (lane >> 2);
                const int m0 = bm + rl, m1 = m0 + 8;
                #pragma unroll
                for (int ni = 0; ni < 8; ni++) {
                    const int c = ni * 8 + 2 * (lane & 3);
                    float bz0 = __ldg(&bias[c]), bz1 = __ldg(&bias[c + 1]);
                    float2 e0 = *reinterpret_cast<const float2*>(eps + (size_t)m0 * ACT_D + c);
                    float2 e1 = *reinterpret_cast<const float2*>(eps + (size_t)m1 * ACT_D + c);
                    float2 a01 = __half22float2(*reinterpret_cast<__half2*>(&acc[mi][ni][0]));
                    float2 a23 = __half22float2(*reinterpret_cast<__half2*>(&acc[mi][ni][1]));
                    float mus[4] = {
                        fmaf(a01.x, scale, bz0), fmaf(a01.y, scale, bz1),
                        fmaf(a23.x, scale, bz0), fmaf(a23.y, scale, bz1)};
                    const int rr[4] = {rl, rl, rl + 8, rl + 8};
                    const int cc[4] = {c, c + 1, c, c + 1};
                    const float ev[4] = {e0.x, e0.y, e1.x, e1.y};
                    float av[4];
                    #pragma unroll
                    for (int e = 0; e < 4; e++) {
                        float sd = std_s[rr[e] * LSS + cc[e]];
                        float ls = ls_s[rr[e] * LSS + cc[e]];
                        float pi = fmaf(sd, ev[e], mus[e]);
                        av[e] = tanhf(pi);
                        float z  = -2.0f * pi;
                        float sp = fmaxf(z, 0.0f) + log1pf(expf(-fabsf(z)));
                        lp[mi][e >> 1] += fmaf(-0.5f * ev[e], ev[e], -ls)
                                        - 0.91893853320467274178f
                                        - 2.0f * (0.69314718055994530942f - pi - sp);
                    }
                    *reinterpret_cast<float2*>(action + (size_t)m0 * ACT_D + c) = make_float2(av[0], av[1]);
                    *reinterpret_cast<float2*>(action + (size_t)m1 * ACT_D + c) = make_float2(av[2], av[3]);
                }
            }
            #pragma unroll
            for (int mi = 0; mi < 2; mi++)
                #pragma unroll
                for (int h = 0; h < 2; h++) {
                    lp[mi][h] += __shfl_xor_sync(0xffffffffu, lp[mi][h], 1);
                    lp[mi][h] += __shfl_xor_sync(0xffffffffu, lp[mi][h], 2);
                }
            if ((lane & 3) == 0) {
                #pragma unroll
                for (int mi = 0; mi < 2; mi++) {
                    const int rl = wm + mi * 16 + (lane >> 2);
                    logp[bm + rl]     = lp[mi][0];
                    logp[bm + rl + 8] = lp[mi][1];
                }
            }
        }
    }
}

// ---------------- launch ----------------
extern "C" void kernel_launch(void* const* d_in, const int* in_sizes, int n_in,
                              void* d_out, int out_size) {
    const float* obs = (const float*)d_in[0];
    const float* eps = (const float*)d_in[1];
    const float* W1  = (const float*)d_in[2];
    const float* b1  = (const float*)d_in[3];
    const float* W2  = (const float*)d_in[4];
    const float* b2  = (const float*)d_in[5];
    const float* W3  = (const float*)d_in[6];
    const float* b3  = (const float*)d_in[7];
    float* out = (float*)d_out;

    void *xb, *h1, *h2, *w1, *w2, *w3, *b1q, *b2q, *b3q, *sc;
    cudaGetSymbolAddress(&xb,  g_xb);
    cudaGetSymbolAddress(&h1,  g_h1);
    cudaGetSymbolAddress(&h2,  g_h2);
    cudaGetSymbolAddress(&w1,  g_w1);
    cudaGetSymbolAddress(&w2,  g_w2);
    cudaGetSymbolAddress(&w3,  g_w3);
    cudaGetSymbolAddress(&b1q, g_b1q);
    cudaGetSymbolAddress(&b2q, g_b2q);
    cudaGetSymbolAddress(&b3q, g_b3q);
    cudaGetSymbolAddress(&sc,  g_scales);

    const unsigned SMEM = 3u * 32768u;   // 96 KB -> 2 CTAs/SM
    cudaFuncSetAttribute((const void*)gemm_tn<0>,
                         cudaFuncAttributeMaxDynamicSharedMemorySize, SMEM);
    cudaFuncSetAttribute((const void*)gemm_tn<1>,
                         cudaFuncAttributeMaxDynamicSharedMemorySize, SMEM);

    zero_absmax_kernel<<<1, 32>>>();
    absmax3_kernel<<<208, 256>>>((const float4*)W1, (const float4*)W2, (const float4*)W3);
    prep_kernel<<<1, 1024>>>(b1, b2, b3);
    quant3_kernel<<<208, 256>>>((const float4*)W1, (const float4*)W2, (const float4*)W3);
    cvt_obs4_kernel<<<4096, 256>>>((const float4*)obs, (uint2*)xb, (B_ROWS * OBS_D) / 4);

    // layer 1: [32768,512] @ [1024,512]^T -> relu fp16 (x4096)
    gemm_tn<0><<<dim3(H1_D / 128, B_ROWS / 128), 256, SMEM>>>(
        (const __half*)xb, (const __half*)w1, (__half*)h1,
        (const float*)b1q, (const float*)sc + 0, OBS_D, H1_D, nullptr, nullptr, nullptr);

    // layer 2: [32768,1024] @ [1024,1024]^T -> relu fp16 (x4096)
    gemm_tn<0><<<dim3(H2_D / 128, B_ROWS / 128), 256, SMEM>>>(
        (const __half*)h1, (const __half*)w2, (__half*)h2,
        (const float*)b2q, (const float*)sc + 1, H1_D, H2_D, nullptr, nullptr, nullptr);

    // layer 3 fused with actor math: action + logp straight to d_out
    gemm_tn<1><<<dim3(1, B_ROWS / 128), 256, SMEM>>>(
        (const __half*)h2, (const __half*)w3, nullptr,
        (const float*)b3q, (const float*)sc + 2, H2_D, 0,
        eps, out, out + (size_t)B_ROWS * ACT_D);
}